// round 14
// baseline (speedup 1.0000x reference)
#include <cuda_runtime.h>
#include <math.h>
#include <stdint.h>

#define NE 16
#define NS 64
#define NDM 128
#define NP 2048
#define NB 8
#define NC 256
#define NW 3
#define NV 5

typedef unsigned long long ull;

// ---------------- global scratch ----------------
__device__ int   g_routes[NE][NW];
__device__ float g_wdir[NV];
__device__ float g_aw[NE];
__device__ float g_invT;
__device__ float g_qd[NE][NS][NV];
__device__ float g_kd[NE][NS][NV];
__device__ int   g_idx[NE][NC];
__device__ int   g_cnt[NE];
__device__ float g_qaff[NE][NV][NB][NC];
__device__ float g_kaff[NE][NV][NB][NC];
__device__ float g_kmin[NE][NV][NB][2];
__device__ float g_kmax[NE][NV][NB][2];
__device__ float g_vbuf[NE][NB][NC][NDM];

// ---------------- helpers ----------------
__device__ __forceinline__ float ex2f(float x) {
    float r; asm("ex2.approx.ftz.f32 %0, %1;" : "=f"(r) : "f"(x)); return r;
}
__device__ __forceinline__ float lg2f_(float x) {
    float r; asm("lg2.approx.f32 %0, %1;" : "=f"(r) : "f"(x)); return r;
}
__device__ __forceinline__ ull fma2(ull a, ull b, ull c) {
    ull d; asm("fma.rn.f32x2 %0, %1, %2, %3;" : "=l"(d) : "l"(a), "l"(b), "l"(c)); return d;
}
__device__ __forceinline__ ull pack2(float lo, float hi) {
    ull d; asm("mov.b64 %0, {%1, %2};" : "=l"(d) : "f"(lo), "f"(hi)); return d;
}
__device__ __forceinline__ float2 unpack2(ull v) {
    float2 r; asm("mov.b64 {%0, %1}, %2;" : "=f"(r.x), "=f"(r.y) : "l"(v)); return r;
}
__device__ __forceinline__ float geluf(float x) {
    float x3 = x * x * x;
    return 0.5f * x * (1.0f + tanhf(0.7978845608028654f * (x + 0.044715f * x3)));
}

// ---------------- K0: setup ----------------
__global__ __launch_bounds__(256) void k_setup(
    const float* __restrict__ alpha, const float* __restrict__ penta,
    const float* __restrict__ fusion_w, const float* __restrict__ q_w,
    const float* __restrict__ k_w, const float* __restrict__ temp)
{
    int e = blockIdx.x, t = threadIdx.x;
    __shared__ float dirs[NV][NDM];
    __shared__ float rn[NV];
    int w = t >> 5, lane = t & 31;
    if (w < NV) {
        float s = 0.f;
        for (int d = lane; d < NDM; d += 32) {
            float x = penta[(e * NV + w) * NDM + d];
            s += x * x;
        }
        for (int off = 16; off; off >>= 1) s += __shfl_xor_sync(0xffffffffu, s, off);
        if (lane == 0) rn[w] = rsqrtf(s);
    }
    __syncthreads();
    for (int i = t; i < NV * NDM; i += 256) {
        int v = i >> 7, d = i & 127;
        dirs[v][d] = penta[(e * NV + v) * NDM + d] * rn[v];
    }
    __syncthreads();
    for (int i = t; i < NS * NV; i += 256) {
        int s = i / NV, v = i % NV;
        float aq = 0.f, ak = 0.f;
        for (int d = 0; d < NDM; d++) {
            float dd = dirs[v][d];
            aq += q_w[(e * NS + s) * NDM + d] * dd;
            ak += k_w[(e * NS + s) * NDM + d] * dd;
        }
        g_qd[e][s][v] = aq;
        g_kd[e][s][v] = ak;
    }
    if (e == 0) {
        if (t < NE) g_aw[t] = 1.f / (1.f + expf(-alpha[t]));
        if (t == 0) {
            g_invT = 1.0f / temp[0];
            float mx = -1e30f;
            for (int i = 0; i < NV; i++) mx = fmaxf(mx, fusion_w[i]);
            float ex[NV], sm = 0.f;
            for (int i = 0; i < NV; i++) { ex[i] = expf(fusion_w[i] - mx); sm += ex[i]; }
            for (int i = 0; i < NV; i++) g_wdir[i] = ex[i] / sm;
            float coords[NE];
            for (int i = 0; i < NE; i++) {
                double x = (double)i / 15.0;
                x = fmax(1e-6, fmin(x, 1.0 - 1e-6));
                double val = 0.0, fac = 0.5;
                for (int k = 0; k < 8; k++) {
                    x *= 3.0;
                    int d = (int)x;
                    x -= (double)d;
                    if (d == 2) val += fac;
                    fac *= 0.5;
                }
                coords[i] = (float)val;
            }
            for (int ee = 0; ee < NE; ee++) {
                float key[NE]; int ord[NE];
                for (int i = 0; i < NE; i++) { key[i] = fabsf(coords[i] - coords[ee]); ord[i] = i; }
                for (int i = 1; i < NE; i++) {
                    float kv = key[i]; int ov = ord[i]; int j = i - 1;
                    while (j >= 0 && key[j] > kv) { key[j + 1] = key[j]; ord[j + 1] = ord[j]; j--; }
                    key[j + 1] = kv; ord[j + 1] = ov;
                }
                for (int wv = 0; wv < NW; wv++) g_routes[ee][wv] = ord[wv];
            }
        }
    }
}

// ---------------- K1: dispatch (warp ballot compaction, warp = expert) ----------------
__global__ __launch_bounds__(512) void k_dispatch(const float* __restrict__ fp)
{
    __shared__ float sf[NP];
    int t = threadIdx.x;
    for (int i = t; i < NP; i += 512) sf[i] = fp[i];
    __syncthreads();
    int w = t >> 5, l = t & 31;
    float lo = (float)w / 16.0f, hi = (float)(w + 1) / 16.0f;
    unsigned lmask = (1u << l) - 1u;
    // pass 1: valid tokens in index order
    int cnt = 0;
    for (int base = 0; base < NP; base += 32) {
        float f = sf[base + l];
        bool m = (f >= lo) && ((w == NE - 1) ? (f <= hi) : (f < hi));
        unsigned bal = __ballot_sync(0xffffffffu, m);
        if (m) {
            int pos = cnt + __popc(bal & lmask);
            if (pos < NC) g_idx[w][pos] = base + l;
        }
        cnt += __popc(bal);
    }
    int vcnt = min(cnt, NC);
    if (l == 0) g_cnt[w] = vcnt;
    // pass 2: invalid tokens fill the remainder (index order)
    cnt = vcnt;
    for (int base = 0; base < NP && cnt < NC; base += 32) {
        float f = sf[base + l];
        bool m = (f >= lo) && ((w == NE - 1) ? (f <= hi) : (f < hi));
        bool im = !m;
        unsigned bal = __ballot_sync(0xffffffffu, im);
        if (im) {
            int pos = cnt + __popc(bal & lmask);
            if (pos < NC) g_idx[w][pos] = base + l;
        }
        cnt += __popc(bal);
    }
}

// ---------------- K zero output ----------------
__global__ __launch_bounds__(256) void k_zero(float* __restrict__ out, int n4)
{
    int i = blockIdx.x * blockDim.x + threadIdx.x;
    if (i < n4) reinterpret_cast<float4*>(out)[i] = make_float4(0.f, 0.f, 0.f, 0.f);
}

// ---------------- K2: gather + gate + affinities + V projection ----------------
// grid (E, B, 2): each block does 128 rows of the 256-row tile.
struct __align__(16) Smem2 {
    float featsT[NS][132];   // [s][local row], 33792 B
    float vw[NS][NDM];       // 32768 B
    float qkd[NS][12];       // qd[0..4], kd[5..9]
    float w1[NS][16];
    float b1[16];
    float w2[16];
    float red[2][NV][4];     // [max/min][v][warp]
    int   idxs[128];
    float b2;
};

__global__ __launch_bounds__(256) void k_featproc(
    const float* __restrict__ tokens, const float* __restrict__ gw1,
    const float* __restrict__ gb1, const float* __restrict__ gw2,
    const float* __restrict__ gb2, const float* __restrict__ vwg)
{
    extern __shared__ char smraw[];
    Smem2& Sm = *reinterpret_cast<Smem2*>(smraw);
    int e = blockIdx.x, b = blockIdx.y, half = blockIdx.z, t = threadIdx.x;
    int i0 = half * 128;
    int cnt = g_cnt[e];
    int nvloc = cnt - i0;
    if (nvloc < 0) nvloc = 0;
    if (nvloc > 128) nvloc = 128;

    if (nvloc == 0) {
        // fast path: everything in this half is invalid -> write safe zeros
        float4 z4 = make_float4(0.f, 0.f, 0.f, 0.f);
        float4* vb = reinterpret_cast<float4*>(&g_vbuf[e][b][i0][0]);
        for (int idx = t; idx < 128 * 32; idx += 256) vb[idx] = z4;
        for (int idx = t; idx < NV * 128; idx += 256) {
            int v = idx >> 7, ii = idx & 127;
            g_qaff[e][v][b][i0 + ii] = 0.f;
            g_kaff[e][v][b][i0 + ii] = 0.f;
        }
        if (t < NV) {
            g_kmax[e][t][b][half] = -INFINITY;
            g_kmin[e][t][b][half] = INFINITY;
        }
        return;
    }

    // ---- loads ----
    if (t < 128) Sm.idxs[t] = g_idx[e][i0 + t];
    for (int idx = t; idx < NS * 16; idx += 256) Sm.w1[idx >> 4][idx & 15] = gw1[e * NS * 16 + idx];
    if (t < 16) { Sm.b1[t] = gb1[e * 16 + t]; Sm.w2[t] = gw2[e * 16 + t]; }
    if (t == 0) Sm.b2 = gb2[e];
    for (int idx = t; idx < NS * NV; idx += 256) {
        int s = idx / NV, v = idx % NV;
        Sm.qkd[s][v]     = g_qd[e][s][v];
        Sm.qkd[s][5 + v] = g_kd[e][s][v];
    }
    {
        const float4* src = reinterpret_cast<const float4*>(vwg + e * NS * NDM);
        float4* dst = reinterpret_cast<float4*>(&Sm.vw[0][0]);
        for (int idx = t; idx < NS * NDM / 4; idx += 256) dst[idx] = src[idx];
    }
    __syncthreads();

    // ---- gather (warp per row); zero rows beyond cnt ----
    {
        int w = t >> 5, l = t & 31;
        for (int r = w; r < 128; r += 8) {
            float2 v2 = make_float2(0.f, 0.f);
            if (r < nvloc) {
                const float* src = tokens + ((size_t)b * NP + Sm.idxs[r]) * 1024 + e * NS;
                v2 = reinterpret_cast<const float2*>(src)[l];
            }
            Sm.featsT[2 * l][r]     = v2.x;
            Sm.featsT[2 * l + 1][r] = v2.y;
        }
    }
    __syncthreads();

    // ---- gate + scale + affinities (t < 128, row t) ----
    float aw = g_aw[e];
    if (t < 128) {
        int i = t;
        ull h2[8];
#pragma unroll
        for (int k = 0; k < 8; k++) h2[k] = pack2(Sm.b1[2 * k], Sm.b1[2 * k + 1]);
        for (int s = 0; s < NS; s++) {
            float f = Sm.featsT[s][i];
            ull f2 = pack2(f, f);
            const ulonglong2* wp = reinterpret_cast<const ulonglong2*>(&Sm.w1[s][0]);
#pragma unroll
            for (int j = 0; j < 4; j++) {
                ulonglong2 wv = wp[j];
                h2[2 * j]     = fma2(f2, wv.x, h2[2 * j]);
                h2[2 * j + 1] = fma2(f2, wv.y, h2[2 * j + 1]);
            }
        }
        float o = Sm.b2;
#pragma unroll
        for (int k = 0; k < 8; k++) {
            float2 hh = unpack2(h2[k]);
            o += geluf(hh.x) * Sm.w2[2 * k] + geluf(hh.y) * Sm.w2[2 * k + 1];
        }
        float gsig  = 1.f / (1.f + __expf(-o));
        float scale = gsig * aw + (1.f - aw);

        float qa[NV], ka[NV];
#pragma unroll
        for (int v = 0; v < NV; v++) { qa[v] = 0.f; ka[v] = 0.f; }
        for (int s = 0; s < NS; s++) {
            float f = Sm.featsT[s][i] * scale;
            Sm.featsT[s][i] = f;
            float4 c0 = *reinterpret_cast<const float4*>(&Sm.qkd[s][0]);
            float4 c1 = *reinterpret_cast<const float4*>(&Sm.qkd[s][4]);
            float4 c2 = *reinterpret_cast<const float4*>(&Sm.qkd[s][8]);
            qa[0] += f * c0.x; qa[1] += f * c0.y; qa[2] += f * c0.z; qa[3] += f * c0.w;
            qa[4] += f * c1.x;
            ka[0] += f * c1.y; ka[1] += f * c1.z; ka[2] += f * c1.w;
            ka[3] += f * c2.x; ka[4] += f * c2.y;
        }
        bool vl = (i < nvloc);
#pragma unroll
        for (int v = 0; v < NV; v++) {
            g_qaff[e][v][b][i0 + i] = qa[v];
            g_kaff[e][v][b][i0 + i] = ka[v];
        }
        int w = t >> 5, lane = t & 31;
#pragma unroll
        for (int v = 0; v < NV; v++) {
            float kmx = vl ? ka[v] : -INFINITY;
            float kmn = vl ? ka[v] :  INFINITY;
            for (int off = 16; off; off >>= 1) {
                kmx = fmaxf(kmx, __shfl_xor_sync(0xffffffffu, kmx, off));
                kmn = fminf(kmn, __shfl_xor_sync(0xffffffffu, kmn, off));
            }
            if (lane == 0) { Sm.red[0][v][w] = kmx; Sm.red[1][v][w] = kmn; }
        }
    }
    __syncthreads();
    if (t < NV) {
        float mx = -INFINITY, mn = INFINITY;
        for (int w = 0; w < 4; w++) {
            mx = fmaxf(mx, Sm.red[0][t][w]);
            mn = fminf(mn, Sm.red[1][t][w]);
        }
        g_kmax[e][t][b][half] = mx;
        g_kmin[e][t][b][half] = mn;
    }

    // ---- V GEMM: 128x128 = featsT^T(128x64) @ vw(64x128), f32x2 ----
    int lane = t & 31, wi = t >> 5;
    for (int pass = 0; pass < 2; pass++) {
        int r0 = pass * 64 + wi * 8;
        ull acc[4][4];
#pragma unroll
        for (int rp = 0; rp < 4; rp++)
#pragma unroll
            for (int c = 0; c < 4; c++) acc[rp][c] = 0ull;
#pragma unroll 4
        for (int k = 0; k < NS; k++) {
            ulonglong2 a01 = *reinterpret_cast<const ulonglong2*>(&Sm.featsT[k][r0]);
            ulonglong2 a23 = *reinterpret_cast<const ulonglong2*>(&Sm.featsT[k][r0 + 4]);
            float4 bv = *reinterpret_cast<const float4*>(&Sm.vw[k][lane * 4]);
            ull ar[4] = {a01.x, a01.y, a23.x, a23.y};
            ull bc[4] = {pack2(bv.x, bv.x), pack2(bv.y, bv.y), pack2(bv.z, bv.z), pack2(bv.w, bv.w)};
#pragma unroll
            for (int rp = 0; rp < 4; rp++)
#pragma unroll
                for (int c = 0; c < 4; c++) acc[rp][c] = fma2(ar[rp], bc[c], acc[rp][c]);
        }
#pragma unroll
        for (int rp = 0; rp < 4; rp++) {
            float2 u0 = unpack2(acc[rp][0]), u1 = unpack2(acc[rp][1]);
            float2 u2 = unpack2(acc[rp][2]), u3 = unpack2(acc[rp][3]);
            int row = r0 + rp * 2;
            float* d0 = &g_vbuf[e][b][i0 + row][lane * 4];
            float* d1 = &g_vbuf[e][b][i0 + row + 1][lane * 4];
            *reinterpret_cast<float4*>(d0) = make_float4(u0.x, u1.x, u2.x, u3.x);
            *reinterpret_cast<float4*>(d1) = make_float4(u0.y, u1.y, u2.y, u3.y);
        }
    }
}

// ---------------- K3: fused multi-direction attention ----------------
struct __align__(16) Smem3 {
    float vchunk[32][132];   // 16896
    float wsub[32][68];      // 8704
    float kall[NV][NW * NC]; // 15360
    float kbias[NW * NC];    // 3072
    float q2[NV][64];
    float m2[NV][64];
    float Cc[NV][64];
    float zp[NV][4][64];
    float kmaxc[NV];
    float kminc[NV];
    float wdirs[NV];
    int   idxs[64];
    int   cnt3[NW];
};

__global__ __launch_bounds__(256) void k_attn(float* __restrict__ out)
{
    int e = blockIdx.x, b = blockIdx.y, it = blockIdx.z, t = threadIdx.x;
    int cnte = g_cnt[e];
    int i0 = it * 64;
    if (i0 >= cnte) return;

    extern __shared__ char smraw[];
    Smem3& Sm = *reinterpret_cast<Smem3*>(smraw);

    int nbs[NW] = {g_routes[e][0], g_routes[e][1], g_routes[e][2]};

    if (t < NW) Sm.cnt3[t] = g_cnt[nbs[t]];
    if (t < NV) {
        Sm.wdirs[t] = g_wdir[t];
        float mx = -INFINITY, mn = INFINITY;
        for (int n = 0; n < NW; n++)
            for (int h = 0; h < 2; h++) {
                mx = fmaxf(mx, g_kmax[nbs[n]][t][b][h]);
                mn = fminf(mn, g_kmin[nbs[n]][t][b][h]);
            }
        Sm.kmaxc[t] = mx;
        Sm.kminc[t] = mn;
    }
    for (int idx = t; idx < 960; idx += 256) {
        int v = idx / 192, r = idx % 192, n = r >> 6, c4 = r & 63;
        float4 val = *reinterpret_cast<const float4*>(&g_kaff[nbs[n]][v][b][c4 * 4]);
        *reinterpret_cast<float4*>(&Sm.kall[v][n * 256 + c4 * 4]) = val;
    }
    float invTl2 = g_invT * 1.4426950408889634f;
    for (int idx = t; idx < NV * 64; idx += 256) {
        int v = idx >> 6, ii = idx & 63;
        Sm.q2[v][ii] = g_qaff[e][v][b][i0 + ii] * invTl2;
    }
    if (t < 64) Sm.idxs[t] = g_idx[e][i0 + t];
    __syncthreads();
    for (int j = t; j < NW * NC; j += 256)
        Sm.kbias[j] = ((j & 255) < Sm.cnt3[j >> 8]) ? 0.f : -1e30f;
    __syncthreads();

    // ---- Pass A: per-(row, dir) normalizer in log2 domain ----
    {
        int ii = t & 63, grp = t >> 6;
#pragma unroll
        for (int v = 0; v < NV; v++) {
            float q = Sm.q2[v][ii];
            float m = fmaxf(q * Sm.kmaxc[v], q * Sm.kminc[v]);
            if (grp == 0) Sm.m2[v][ii] = m;
            float z = 0.f;
            int jb = grp * 192;
            for (int j4 = jb; j4 < jb + 192; j4 += 4) {
                float4 kb = *reinterpret_cast<const float4*>(&Sm.kbias[j4]);
                if (kb.x == 0.f) {   // validity is a prefix within each 4-group
                    float4 kv = *reinterpret_cast<const float4*>(&Sm.kall[v][j4]);
                    z += ex2f(fmaf(q, kv.x, kb.x - m));
                    z += ex2f(fmaf(q, kv.y, kb.y - m));
                    z += ex2f(fmaf(q, kv.z, kb.z - m));
                    z += ex2f(fmaf(q, kv.w, kb.w - m));
                }
            }
            Sm.zp[v][grp][ii] = z;
        }
    }
    __syncthreads();
    for (int idx = t; idx < NV * 64; idx += 256) {
        int v = idx / 64, iL = idx % 64;
        float Z = Sm.zp[v][0][iL] + Sm.zp[v][1][iL] + Sm.zp[v][2][iL] + Sm.zp[v][3][iL];
        Sm.Cc[v][iL] = (Z > 0.f) ? (lg2f_(Sm.wdirs[v] / Z) - Sm.m2[v][iL]) : -1e30f;
    }
    __syncthreads();

    // ---- Pass B: combined-weight GEMM in 32-row chunks, f32x2 ----
    int i = t & 63, jgrp = t >> 6;
    float q2r[NV], Cr[NV];
#pragma unroll
    for (int v = 0; v < NV; v++) { q2r[v] = Sm.q2[v][i]; Cr[v] = Sm.Cc[v][i]; }

    int lane = t & 31, w = t >> 5;
    ull acc[4][4];
#pragma unroll
    for (int rp = 0; rp < 4; rp++)
#pragma unroll
        for (int c = 0; c < 4; c++) acc[rp][c] = 0ull;

    for (int ch = 0; ch < 24; ch++) {
        int n = ch >> 3, jl = (ch & 7) * 32;
        int cn = Sm.cnt3[n];
        if (jl >= cn) continue;
        __syncthreads();   // previous chunk's GEMM reads done

        // load V chunk (32 x 128 f32) from L2-resident vbuf
        {
            const float4* vsrc = reinterpret_cast<const float4*>(&g_vbuf[nbs[n]][b][jl][0]);
#pragma unroll
            for (int k4 = 0; k4 < 4; k4++) {
                int idx = t + k4 * 256;
                int row = idx >> 5, c4 = idx & 31;
                *reinterpret_cast<float4*>(&Sm.vchunk[row][c4 * 4]) = vsrc[idx];
            }
        }
        // combined weights W[j][i] = sum_v exp2(q2*k + C)
        {
#pragma unroll
            for (int jj = 0; jj < 8; jj++) {
                int jloc = jgrp * 8 + jj;
                int j = n * 256 + jl + jloc;
                float wv = 0.f;
#pragma unroll
                for (int v = 0; v < NV; v++)
                    wv += ex2f(fmaf(q2r[v], Sm.kall[v][j], Cr[v]));
                if (jl + jloc >= cn) wv = 0.f;
                Sm.wsub[jloc][i] = wv;
            }
        }
        __syncthreads();
        // GEMM: out(64x128) += wsub(32x64)^T-as-[k][i] @ vchunk(32x128)
#pragma unroll 4
        for (int k = 0; k < 32; k++) {
            ulonglong2 a01 = *reinterpret_cast<const ulonglong2*>(&Sm.wsub[k][w * 8]);
            ulonglong2 a23 = *reinterpret_cast<const ulonglong2*>(&Sm.wsub[k][w * 8 + 4]);
            float4 bv = *reinterpret_cast<const float4*>(&Sm.vchunk[k][lane * 4]);
            ull ar[4] = {a01.x, a01.y, a23.x, a23.y};
            ull bc[4] = {pack2(bv.x, bv.x), pack2(bv.y, bv.y), pack2(bv.z, bv.z), pack2(bv.w, bv.w)};
#pragma unroll
            for (int rp = 0; rp < 4; rp++)
#pragma unroll
                for (int c = 0; c < 4; c++) acc[rp][c] = fma2(ar[rp], bc[c], acc[rp][c]);
        }
    }

    // ---- store valid rows (each token owned by exactly one expert) ----
#pragma unroll
    for (int rp = 0; rp < 4; rp++) {
        int row = w * 8 + rp * 2;
        float2 u0 = unpack2(acc[rp][0]), u1 = unpack2(acc[rp][1]);
        float2 u2 = unpack2(acc[rp][2]), u3 = unpack2(acc[rp][3]);
        if (i0 + row < cnte) {
            float* dst = out + ((size_t)b * NP + Sm.idxs[row]) * NDM + lane * 4;
            *reinterpret_cast<float4*>(dst) = make_float4(u0.x, u1.x, u2.x, u3.x);
        }
        if (i0 + row + 1 < cnte) {
            float* dst = out + ((size_t)b * NP + Sm.idxs[row + 1]) * NDM + lane * 4;
            *reinterpret_cast<float4*>(dst) = make_float4(u0.y, u1.y, u2.y, u3.y);
        }
    }
}

// ---------------- launch ----------------
extern "C" void kernel_launch(void* const* d_in, const int* in_sizes, int n_in,
                              void* d_out, int out_size)
{
    const float* tokens  = (const float*)d_in[0];
    const float* fingerp = (const float*)d_in[1];
    const float* alpha   = (const float*)d_in[2];
    const float* gw1     = (const float*)d_in[3];
    const float* gb1     = (const float*)d_in[4];
    const float* gw2     = (const float*)d_in[5];
    const float* gb2     = (const float*)d_in[6];
    const float* q_w     = (const float*)d_in[7];
    const float* k_w     = (const float*)d_in[8];
    const float* v_w     = (const float*)d_in[9];
    const float* penta   = (const float*)d_in[10];
    const float* fusion  = (const float*)d_in[11];
    const float* temp    = (const float*)d_in[12];
    float* out = (float*)d_out;

    cudaFuncSetAttribute(k_featproc, cudaFuncAttributeMaxDynamicSharedMemorySize, (int)sizeof(Smem2));
    cudaFuncSetAttribute(k_attn,     cudaFuncAttributeMaxDynamicSharedMemorySize, (int)sizeof(Smem3));

    k_setup<<<NE, 256>>>(alpha, penta, fusion, q_w, k_w, temp);
    k_dispatch<<<1, 512>>>(fingerp);
    int n4 = out_size / 4;
    k_zero<<<(n4 + 255) / 256, 256>>>(out, n4);
    k_featproc<<<dim3(NE, NB, 2), 256, sizeof(Smem2)>>>(tokens, gw1, gb1, gw2, gb2, v_w);
    k_attn<<<dim3(NE, NB, 4), 256, sizeof(Smem3)>>>(out);
}

// round 15
// speedup vs baseline: 1.0016x; 1.0016x over previous
#include <cuda_runtime.h>
#include <math.h>
#include <stdint.h>

#define NE 16
#define NS 64
#define NDM 128
#define NP 2048
#define NB 8
#define NC 256
#define NW 3
#define NV 5

typedef unsigned long long ull;

// ---------------- global scratch ----------------
__device__ int   g_routes[NE][NW];
__device__ float g_wdir[NV];
__device__ float g_aw[NE];
__device__ float g_invT;
__device__ float g_qd[NE][NS][NV];
__device__ float g_kd[NE][NS][NV];
__device__ int   g_idx[NE][NC];
__device__ int   g_cnt[NE];
__device__ float g_qaff[NE][NV][NB][NC];
__device__ float g_kaff[NE][NV][NB][NC];
__device__ float g_kmin[NE][NV][NB][2];
__device__ float g_kmax[NE][NV][NB][2];
__device__ float g_vbuf[NE][NB][NC][NDM];

// ---------------- helpers ----------------
__device__ __forceinline__ float ex2f(float x) {
    float r; asm("ex2.approx.ftz.f32 %0, %1;" : "=f"(r) : "f"(x)); return r;
}
__device__ __forceinline__ float lg2f_(float x) {
    float r; asm("lg2.approx.f32 %0, %1;" : "=f"(r) : "f"(x)); return r;
}
__device__ __forceinline__ ull fma2(ull a, ull b, ull c) {
    ull d; asm("fma.rn.f32x2 %0, %1, %2, %3;" : "=l"(d) : "l"(a), "l"(b), "l"(c)); return d;
}
__device__ __forceinline__ ull pack2(float lo, float hi) {
    ull d; asm("mov.b64 %0, {%1, %2};" : "=l"(d) : "f"(lo), "f"(hi)); return d;
}
__device__ __forceinline__ float2 unpack2(ull v) {
    float2 r; asm("mov.b64 {%0, %1}, %2;" : "=f"(r.x), "=f"(r.y) : "l"(v)); return r;
}
__device__ __forceinline__ float geluf(float x) {
    float x3 = x * x * x;
    return 0.5f * x * (1.0f + tanhf(0.7978845608028654f * (x + 0.044715f * x3)));
}

// ---------------- K0: setup ----------------
__global__ __launch_bounds__(256) void k_setup(
    const float* __restrict__ alpha, const float* __restrict__ penta,
    const float* __restrict__ fusion_w, const float* __restrict__ q_w,
    const float* __restrict__ k_w, const float* __restrict__ temp)
{
    int e = blockIdx.x, t = threadIdx.x;
    __shared__ float dirs[NV][NDM];
    __shared__ float rn[NV];
    int w = t >> 5, lane = t & 31;
    if (w < NV) {
        float s = 0.f;
        for (int d = lane; d < NDM; d += 32) {
            float x = penta[(e * NV + w) * NDM + d];
            s += x * x;
        }
        for (int off = 16; off; off >>= 1) s += __shfl_xor_sync(0xffffffffu, s, off);
        if (lane == 0) rn[w] = rsqrtf(s);
    }
    __syncthreads();
    for (int i = t; i < NV * NDM; i += 256) {
        int v = i >> 7, d = i & 127;
        dirs[v][d] = penta[(e * NV + v) * NDM + d] * rn[v];
    }
    __syncthreads();
    for (int i = t; i < NS * NV; i += 256) {
        int s = i / NV, v = i % NV;
        float aq = 0.f, ak = 0.f;
        for (int d = 0; d < NDM; d++) {
            float dd = dirs[v][d];
            aq += q_w[(e * NS + s) * NDM + d] * dd;
            ak += k_w[(e * NS + s) * NDM + d] * dd;
        }
        g_qd[e][s][v] = aq;
        g_kd[e][s][v] = ak;
    }
    if (e == 0) {
        if (t < NE) g_aw[t] = 1.f / (1.f + expf(-alpha[t]));
        if (t == 0) {
            g_invT = 1.0f / temp[0];
            float mx = -1e30f;
            for (int i = 0; i < NV; i++) mx = fmaxf(mx, fusion_w[i]);
            float ex[NV], sm = 0.f;
            for (int i = 0; i < NV; i++) { ex[i] = expf(fusion_w[i] - mx); sm += ex[i]; }
            for (int i = 0; i < NV; i++) g_wdir[i] = ex[i] / sm;
            float coords[NE];
            for (int i = 0; i < NE; i++) {
                double x = (double)i / 15.0;
                x = fmax(1e-6, fmin(x, 1.0 - 1e-6));
                double val = 0.0, fac = 0.5;
                for (int k = 0; k < 8; k++) {
                    x *= 3.0;
                    int d = (int)x;
                    x -= (double)d;
                    if (d == 2) val += fac;
                    fac *= 0.5;
                }
                coords[i] = (float)val;
            }
            for (int ee = 0; ee < NE; ee++) {
                float key[NE]; int ord[NE];
                for (int i = 0; i < NE; i++) { key[i] = fabsf(coords[i] - coords[ee]); ord[i] = i; }
                for (int i = 1; i < NE; i++) {
                    float kv = key[i]; int ov = ord[i]; int j = i - 1;
                    while (j >= 0 && key[j] > kv) { key[j + 1] = key[j]; ord[j + 1] = ord[j]; j--; }
                    key[j + 1] = kv; ord[j + 1] = ov;
                }
                for (int wv = 0; wv < NW; wv++) g_routes[ee][wv] = ord[wv];
            }
        }
    }
}

// ---------------- K1: dispatch (warp ballot compaction, warp = expert) ----------------
__global__ __launch_bounds__(512) void k_dispatch(const float* __restrict__ fp)
{
    __shared__ float sf[NP];
    int t = threadIdx.x;
    for (int i = t; i < NP; i += 512) sf[i] = fp[i];
    __syncthreads();
    int w = t >> 5, l = t & 31;
    float lo = (float)w / 16.0f, hi = (float)(w + 1) / 16.0f;
    unsigned lmask = (1u << l) - 1u;
    // pass 1: valid tokens in index order
    int cnt = 0;
    for (int base = 0; base < NP; base += 32) {
        float f = sf[base + l];
        bool m = (f >= lo) && ((w == NE - 1) ? (f <= hi) : (f < hi));
        unsigned bal = __ballot_sync(0xffffffffu, m);
        if (m) {
            int pos = cnt + __popc(bal & lmask);
            if (pos < NC) g_idx[w][pos] = base + l;
        }
        cnt += __popc(bal);
    }
    int vcnt = min(cnt, NC);
    if (l == 0) g_cnt[w] = vcnt;
    // pass 2: invalid tokens fill the remainder (index order)
    cnt = vcnt;
    for (int base = 0; base < NP && cnt < NC; base += 32) {
        float f = sf[base + l];
        bool m = (f >= lo) && ((w == NE - 1) ? (f <= hi) : (f < hi));
        bool im = !m;
        unsigned bal = __ballot_sync(0xffffffffu, im);
        if (im) {
            int pos = cnt + __popc(bal & lmask);
            if (pos < NC) g_idx[w][pos] = base + l;
        }
        cnt += __popc(bal);
    }
}

// ---------------- K zero output ----------------
__global__ __launch_bounds__(256) void k_zero(float* __restrict__ out, int n4)
{
    int i = blockIdx.x * blockDim.x + threadIdx.x;
    if (i < n4) reinterpret_cast<float4*>(out)[i] = make_float4(0.f, 0.f, 0.f, 0.f);
}

// ---------------- K2: gather + gate + affinities + V projection ----------------
// grid (E, B, 2): each block does 128 rows of the 256-row tile.
struct __align__(16) Smem2 {
    float featsT[NS][132];   // [s][local row], 33792 B
    float vw[NS][NDM];       // 32768 B
    float qkd[NS][12];       // qd[0..4], kd[5..9]
    float w1[NS][16];
    float b1[16];
    float w2[16];
    float red[2][NV][4];     // [max/min][v][warp]
    int   idxs[128];
    float b2;
};

__global__ __launch_bounds__(256) void k_featproc(
    const float* __restrict__ tokens, const float* __restrict__ gw1,
    const float* __restrict__ gb1, const float* __restrict__ gw2,
    const float* __restrict__ gb2, const float* __restrict__ vwg)
{
    extern __shared__ char smraw[];
    Smem2& Sm = *reinterpret_cast<Smem2*>(smraw);
    int e = blockIdx.x, b = blockIdx.y, half = blockIdx.z, t = threadIdx.x;
    int i0 = half * 128;
    int cnt = g_cnt[e];
    int nvloc = cnt - i0;
    if (nvloc < 0) nvloc = 0;
    if (nvloc > 128) nvloc = 128;

    if (nvloc == 0) {
        // fast path: everything in this half is invalid -> write safe zeros
        float4 z4 = make_float4(0.f, 0.f, 0.f, 0.f);
        float4* vb = reinterpret_cast<float4*>(&g_vbuf[e][b][i0][0]);
        for (int idx = t; idx < 128 * 32; idx += 256) vb[idx] = z4;
        for (int idx = t; idx < NV * 128; idx += 256) {
            int v = idx >> 7, ii = idx & 127;
            g_qaff[e][v][b][i0 + ii] = 0.f;
            g_kaff[e][v][b][i0 + ii] = 0.f;
        }
        if (t < NV) {
            g_kmax[e][t][b][half] = -INFINITY;
            g_kmin[e][t][b][half] = INFINITY;
        }
        return;
    }

    // ---- loads ----
    if (t < 128) Sm.idxs[t] = g_idx[e][i0 + t];
    for (int idx = t; idx < NS * 16; idx += 256) Sm.w1[idx >> 4][idx & 15] = gw1[e * NS * 16 + idx];
    if (t < 16) { Sm.b1[t] = gb1[e * 16 + t]; Sm.w2[t] = gw2[e * 16 + t]; }
    if (t == 0) Sm.b2 = gb2[e];
    for (int idx = t; idx < NS * NV; idx += 256) {
        int s = idx / NV, v = idx % NV;
        Sm.qkd[s][v]     = g_qd[e][s][v];
        Sm.qkd[s][5 + v] = g_kd[e][s][v];
    }
    {
        const float4* src = reinterpret_cast<const float4*>(vwg + e * NS * NDM);
        float4* dst = reinterpret_cast<float4*>(&Sm.vw[0][0]);
        for (int idx = t; idx < NS * NDM / 4; idx += 256) dst[idx] = src[idx];
    }
    __syncthreads();

    // ---- gather (warp per row); zero rows beyond cnt ----
    {
        int w = t >> 5, l = t & 31;
        for (int r = w; r < 128; r += 8) {
            float2 v2 = make_float2(0.f, 0.f);
            if (r < nvloc) {
                const float* src = tokens + ((size_t)b * NP + Sm.idxs[r]) * 1024 + e * NS;
                v2 = reinterpret_cast<const float2*>(src)[l];
            }
            Sm.featsT[2 * l][r]     = v2.x;
            Sm.featsT[2 * l + 1][r] = v2.y;
        }
    }
    __syncthreads();

    // ---- gate + scale + affinities (t < 128, row t) ----
    float aw = g_aw[e];
    if (t < 128) {
        int i = t;
        ull h2[8];
#pragma unroll
        for (int k = 0; k < 8; k++) h2[k] = pack2(Sm.b1[2 * k], Sm.b1[2 * k + 1]);
        for (int s = 0; s < NS; s++) {
            float f = Sm.featsT[s][i];
            ull f2 = pack2(f, f);
            const ulonglong2* wp = reinterpret_cast<const ulonglong2*>(&Sm.w1[s][0]);
#pragma unroll
            for (int j = 0; j < 4; j++) {
                ulonglong2 wv = wp[j];
                h2[2 * j]     = fma2(f2, wv.x, h2[2 * j]);
                h2[2 * j + 1] = fma2(f2, wv.y, h2[2 * j + 1]);
            }
        }
        float o = Sm.b2;
#pragma unroll
        for (int k = 0; k < 8; k++) {
            float2 hh = unpack2(h2[k]);
            o += geluf(hh.x) * Sm.w2[2 * k] + geluf(hh.y) * Sm.w2[2 * k + 1];
        }
        float gsig  = 1.f / (1.f + __expf(-o));
        float scale = gsig * aw + (1.f - aw);

        float qa[NV], ka[NV];
#pragma unroll
        for (int v = 0; v < NV; v++) { qa[v] = 0.f; ka[v] = 0.f; }
        for (int s = 0; s < NS; s++) {
            float f = Sm.featsT[s][i] * scale;
            Sm.featsT[s][i] = f;
            float4 c0 = *reinterpret_cast<const float4*>(&Sm.qkd[s][0]);
            float4 c1 = *reinterpret_cast<const float4*>(&Sm.qkd[s][4]);
            float4 c2 = *reinterpret_cast<const float4*>(&Sm.qkd[s][8]);
            qa[0] += f * c0.x; qa[1] += f * c0.y; qa[2] += f * c0.z; qa[3] += f * c0.w;
            qa[4] += f * c1.x;
            ka[0] += f * c1.y; ka[1] += f * c1.z; ka[2] += f * c1.w;
            ka[3] += f * c2.x; ka[4] += f * c2.y;
        }
        bool vl = (i < nvloc);
#pragma unroll
        for (int v = 0; v < NV; v++) {
            g_qaff[e][v][b][i0 + i] = qa[v];
            g_kaff[e][v][b][i0 + i] = ka[v];
        }
        int w = t >> 5, lane = t & 31;
#pragma unroll
        for (int v = 0; v < NV; v++) {
            float kmx = vl ? ka[v] : -INFINITY;
            float kmn = vl ? ka[v] :  INFINITY;
            for (int off = 16; off; off >>= 1) {
                kmx = fmaxf(kmx, __shfl_xor_sync(0xffffffffu, kmx, off));
                kmn = fminf(kmn, __shfl_xor_sync(0xffffffffu, kmn, off));
            }
            if (lane == 0) { Sm.red[0][v][w] = kmx; Sm.red[1][v][w] = kmn; }
        }
    }
    __syncthreads();
    if (t < NV) {
        float mx = -INFINITY, mn = INFINITY;
        for (int w = 0; w < 4; w++) {
            mx = fmaxf(mx, Sm.red[0][t][w]);
            mn = fminf(mn, Sm.red[1][t][w]);
        }
        g_kmax[e][t][b][half] = mx;
        g_kmin[e][t][b][half] = mn;
    }

    // ---- V GEMM: 128x128 = featsT^T(128x64) @ vw(64x128), f32x2 ----
    int lane = t & 31, wi = t >> 5;
    for (int pass = 0; pass < 2; pass++) {
        int r0 = pass * 64 + wi * 8;
        ull acc[4][4];
#pragma unroll
        for (int rp = 0; rp < 4; rp++)
#pragma unroll
            for (int c = 0; c < 4; c++) acc[rp][c] = 0ull;
#pragma unroll 4
        for (int k = 0; k < NS; k++) {
            ulonglong2 a01 = *reinterpret_cast<const ulonglong2*>(&Sm.featsT[k][r0]);
            ulonglong2 a23 = *reinterpret_cast<const ulonglong2*>(&Sm.featsT[k][r0 + 4]);
            float4 bv = *reinterpret_cast<const float4*>(&Sm.vw[k][lane * 4]);
            ull ar[4] = {a01.x, a01.y, a23.x, a23.y};
            ull bc[4] = {pack2(bv.x, bv.x), pack2(bv.y, bv.y), pack2(bv.z, bv.z), pack2(bv.w, bv.w)};
#pragma unroll
            for (int rp = 0; rp < 4; rp++)
#pragma unroll
                for (int c = 0; c < 4; c++) acc[rp][c] = fma2(ar[rp], bc[c], acc[rp][c]);
        }
#pragma unroll
        for (int rp = 0; rp < 4; rp++) {
            float2 u0 = unpack2(acc[rp][0]), u1 = unpack2(acc[rp][1]);
            float2 u2 = unpack2(acc[rp][2]), u3 = unpack2(acc[rp][3]);
            int row = r0 + rp * 2;
            float* d0 = &g_vbuf[e][b][i0 + row][lane * 4];
            float* d1 = &g_vbuf[e][b][i0 + row + 1][lane * 4];
            *reinterpret_cast<float4*>(d0) = make_float4(u0.x, u1.x, u2.x, u3.x);
            *reinterpret_cast<float4*>(d1) = make_float4(u0.y, u1.y, u2.y, u3.y);
        }
    }
}

// ---------------- K3: fused multi-direction attention ----------------
struct __align__(16) Smem3 {
    float vchunk[32][132];   // 16896
    float wsub[32][68];      // 8704
    float kall[NV][NW * NC]; // 15360
    float kbias[NW * NC];    // 3072
    float q2[NV][64];
    float m2[NV][64];
    float Cc[NV][64];
    float zp[NV][4][64];
    float kmaxc[NV];
    float kminc[NV];
    float wdirs[NV];
    int   idxs[64];
    int   cnt3[NW];
};

__global__ __launch_bounds__(256) void k_attn(float* __restrict__ out)
{
    int e = blockIdx.x, b = blockIdx.y, it = blockIdx.z, t = threadIdx.x;
    int cnte = g_cnt[e];
    int i0 = it * 64;
    if (i0 >= cnte) return;

    extern __shared__ char smraw[];
    Smem3& Sm = *reinterpret_cast<Smem3*>(smraw);

    int nbs[NW] = {g_routes[e][0], g_routes[e][1], g_routes[e][2]};

    if (t < NW) Sm.cnt3[t] = g_cnt[nbs[t]];
    if (t < NV) {
        Sm.wdirs[t] = g_wdir[t];
        float mx = -INFINITY, mn = INFINITY;
        for (int n = 0; n < NW; n++)
            for (int h = 0; h < 2; h++) {
                mx = fmaxf(mx, g_kmax[nbs[n]][t][b][h]);
                mn = fminf(mn, g_kmin[nbs[n]][t][b][h]);
            }
        Sm.kmaxc[t] = mx;
        Sm.kminc[t] = mn;
    }
    for (int idx = t; idx < 960; idx += 256) {
        int v = idx / 192, r = idx % 192, n = r >> 6, c4 = r & 63;
        float4 val = *reinterpret_cast<const float4*>(&g_kaff[nbs[n]][v][b][c4 * 4]);
        *reinterpret_cast<float4*>(&Sm.kall[v][n * 256 + c4 * 4]) = val;
    }
    float invTl2 = g_invT * 1.4426950408889634f;
    for (int idx = t; idx < NV * 64; idx += 256) {
        int v = idx >> 6, ii = idx & 63;
        Sm.q2[v][ii] = g_qaff[e][v][b][i0 + ii] * invTl2;
    }
    if (t < 64) Sm.idxs[t] = g_idx[e][i0 + t];
    __syncthreads();
    for (int j = t; j < NW * NC; j += 256)
        Sm.kbias[j] = ((j & 255) < Sm.cnt3[j >> 8]) ? 0.f : -1e30f;
    __syncthreads();

    // ---- Pass A: per-(row, dir) normalizer in log2 domain ----
    {
        int ii = t & 63, grp = t >> 6;
#pragma unroll
        for (int v = 0; v < NV; v++) {
            float q = Sm.q2[v][ii];
            float m = fmaxf(q * Sm.kmaxc[v], q * Sm.kminc[v]);
            if (grp == 0) Sm.m2[v][ii] = m;
            float z = 0.f;
            int jb = grp * 192;
            for (int j4 = jb; j4 < jb + 192; j4 += 4) {
                float4 kb = *reinterpret_cast<const float4*>(&Sm.kbias[j4]);
                if (kb.x == 0.f) {   // validity is a prefix within each 4-group
                    float4 kv = *reinterpret_cast<const float4*>(&Sm.kall[v][j4]);
                    z += ex2f(fmaf(q, kv.x, kb.x - m));
                    z += ex2f(fmaf(q, kv.y, kb.y - m));
                    z += ex2f(fmaf(q, kv.z, kb.z - m));
                    z += ex2f(fmaf(q, kv.w, kb.w - m));
                }
            }
            Sm.zp[v][grp][ii] = z;
        }
    }
    __syncthreads();
    for (int idx = t; idx < NV * 64; idx += 256) {
        int v = idx / 64, iL = idx % 64;
        float Z = Sm.zp[v][0][iL] + Sm.zp[v][1][iL] + Sm.zp[v][2][iL] + Sm.zp[v][3][iL];
        Sm.Cc[v][iL] = (Z > 0.f) ? (lg2f_(Sm.wdirs[v] / Z) - Sm.m2[v][iL]) : -1e30f;
    }
    __syncthreads();

    // ---- Pass B: combined-weight GEMM in 32-row chunks, f32x2 ----
    int i = t & 63, jgrp = t >> 6;
    float q2r[NV], Cr[NV];
#pragma unroll
    for (int v = 0; v < NV; v++) { q2r[v] = Sm.q2[v][i]; Cr[v] = Sm.Cc[v][i]; }

    int lane = t & 31, w = t >> 5;
    ull acc[4][4];
#pragma unroll
    for (int rp = 0; rp < 4; rp++)
#pragma unroll
        for (int c = 0; c < 4; c++) acc[rp][c] = 0ull;

    for (int ch = 0; ch < 24; ch++) {
        int n = ch >> 3, jl = (ch & 7) * 32;
        int cn = Sm.cnt3[n];
        if (jl >= cn) continue;
        __syncthreads();   // previous chunk's GEMM reads done

        // load V chunk (32 x 128 f32) from L2-resident vbuf
        {
            const float4* vsrc = reinterpret_cast<const float4*>(&g_vbuf[nbs[n]][b][jl][0]);
#pragma unroll
            for (int k4 = 0; k4 < 4; k4++) {
                int idx = t + k4 * 256;
                int row = idx >> 5, c4 = idx & 31;
                *reinterpret_cast<float4*>(&Sm.vchunk[row][c4 * 4]) = vsrc[idx];
            }
        }
        // combined weights W[j][i] = sum_v exp2(q2*k + C)
        {
#pragma unroll
            for (int jj = 0; jj < 8; jj++) {
                int jloc = jgrp * 8 + jj;
                int j = n * 256 + jl + jloc;
                float wv = 0.f;
#pragma unroll
                for (int v = 0; v < NV; v++)
                    wv += ex2f(fmaf(q2r[v], Sm.kall[v][j], Cr[v]));
                if (jl + jloc >= cn) wv = 0.f;
                Sm.wsub[jloc][i] = wv;
            }
        }
        __syncthreads();
        // GEMM: out(64x128) += wsub(32x64)^T-as-[k][i] @ vchunk(32x128)
#pragma unroll 4
        for (int k = 0; k < 32; k++) {
            ulonglong2 a01 = *reinterpret_cast<const ulonglong2*>(&Sm.wsub[k][w * 8]);
            ulonglong2 a23 = *reinterpret_cast<const ulonglong2*>(&Sm.wsub[k][w * 8 + 4]);
            float4 bv = *reinterpret_cast<const float4*>(&Sm.vchunk[k][lane * 4]);
            ull ar[4] = {a01.x, a01.y, a23.x, a23.y};
            ull bc[4] = {pack2(bv.x, bv.x), pack2(bv.y, bv.y), pack2(bv.z, bv.z), pack2(bv.w, bv.w)};
#pragma unroll
            for (int rp = 0; rp < 4; rp++)
#pragma unroll
                for (int c = 0; c < 4; c++) acc[rp][c] = fma2(ar[rp], bc[c], acc[rp][c]);
        }
    }

    // ---- store valid rows (each token owned by exactly one expert) ----
#pragma unroll
    for (int rp = 0; rp < 4; rp++) {
        int row = w * 8 + rp * 2;
        float2 u0 = unpack2(acc[rp][0]), u1 = unpack2(acc[rp][1]);
        float2 u2 = unpack2(acc[rp][2]), u3 = unpack2(acc[rp][3]);
        if (i0 + row < cnte) {
            float* dst = out + ((size_t)b * NP + Sm.idxs[row]) * NDM + lane * 4;
            *reinterpret_cast<float4*>(dst) = make_float4(u0.x, u1.x, u2.x, u3.x);
        }
        if (i0 + row + 1 < cnte) {
            float* dst = out + ((size_t)b * NP + Sm.idxs[row + 1]) * NDM + lane * 4;
            *reinterpret_cast<float4*>(dst) = make_float4(u0.y, u1.y, u2.y, u3.y);
        }
    }
}

// ---------------- launch ----------------
extern "C" void kernel_launch(void* const* d_in, const int* in_sizes, int n_in,
                              void* d_out, int out_size)
{
    const float* tokens  = (const float*)d_in[0];
    const float* fingerp = (const float*)d_in[1];
    const float* alpha   = (const float*)d_in[2];
    const float* gw1     = (const float*)d_in[3];
    const float* gb1     = (const float*)d_in[4];
    const float* gw2     = (const float*)d_in[5];
    const float* gb2     = (const float*)d_in[6];
    const float* q_w     = (const float*)d_in[7];
    const float* k_w     = (const float*)d_in[8];
    const float* v_w     = (const float*)d_in[9];
    const float* penta   = (const float*)d_in[10];
    const float* fusion  = (const float*)d_in[11];
    const float* temp    = (const float*)d_in[12];
    float* out = (float*)d_out;

    cudaFuncSetAttribute(k_featproc, cudaFuncAttributeMaxDynamicSharedMemorySize, (int)sizeof(Smem2));
    cudaFuncSetAttribute(k_attn,     cudaFuncAttributeMaxDynamicSharedMemorySize, (int)sizeof(Smem3));

    k_setup<<<NE, 256>>>(alpha, penta, fusion, q_w, k_w, temp);
    k_dispatch<<<1, 512>>>(fingerp);
    int n4 = out_size / 4;
    k_zero<<<(n4 + 255) / 256, 256>>>(out, n4);
    k_featproc<<<dim3(NE, NB, 2), 256, sizeof(Smem2)>>>(tokens, gw1, gb1, gw2, gb2, v_w);
    k_attn<<<dim3(NE, NB, 4), 256, sizeof(Smem3)>>>(out);
}

// round 16
// speedup vs baseline: 1.0631x; 1.0614x over previous
#include <cuda_runtime.h>
#include <math.h>
#include <stdint.h>

#define NE 16
#define NS 64
#define NDM 128
#define NP 2048
#define NB 8
#define NC 256
#define NW 3
#define NV 5

typedef unsigned long long ull;

// ---------------- global scratch ----------------
__device__ int   g_routes[NE][NW];
__device__ float g_wdir[NV];
__device__ float g_aw[NE];
__device__ float g_invT;
__device__ float g_qd[NE][NS][NV];
__device__ float g_kd[NE][NS][NV];
__device__ int   g_idx[NE][NC];
__device__ int   g_cnt[NE];
__device__ float g_qaff[NE][NV][NB][NC];
__device__ float g_kaff[NE][NV][NB][NC];
__device__ float g_kmin[NE][NV][NB][2];
__device__ float g_kmax[NE][NV][NB][2];
__device__ float g_vbuf[NE][NB][NC][NDM];

// ---------------- helpers ----------------
__device__ __forceinline__ float ex2f(float x) {
    float r; asm("ex2.approx.ftz.f32 %0, %1;" : "=f"(r) : "f"(x)); return r;
}
__device__ __forceinline__ float lg2f_(float x) {
    float r; asm("lg2.approx.f32 %0, %1;" : "=f"(r) : "f"(x)); return r;
}
__device__ __forceinline__ ull fma2(ull a, ull b, ull c) {
    ull d; asm("fma.rn.f32x2 %0, %1, %2, %3;" : "=l"(d) : "l"(a), "l"(b), "l"(c)); return d;
}
__device__ __forceinline__ ull pack2(float lo, float hi) {
    ull d; asm("mov.b64 %0, {%1, %2};" : "=l"(d) : "f"(lo), "f"(hi)); return d;
}
__device__ __forceinline__ float2 unpack2(ull v) {
    float2 r; asm("mov.b64 {%0, %1}, %2;" : "=f"(r.x), "=f"(r.y) : "l"(v)); return r;
}
__device__ __forceinline__ float geluf(float x) {
    float u = 0.7978845608028654f * (x + 0.044715f * x * x * x);
    float au = fabsf(u);
    float th = 1.f - __fdividef(2.f, __expf(2.f * au) + 1.f);
    th = copysignf(th, u);
    return 0.5f * x * (1.f + th);
}

// ---------------- K0: setup (blocks 0..15) + dispatch (block 16) ----------------
__global__ __launch_bounds__(512) void k_init(
    const float* __restrict__ alpha, const float* __restrict__ penta,
    const float* __restrict__ fusion_w, const float* __restrict__ q_w,
    const float* __restrict__ k_w, const float* __restrict__ temp,
    const float* __restrict__ fp)
{
    int t = threadIdx.x;
    if (blockIdx.x < NE) {
        int e = blockIdx.x;
        __shared__ float dirs[NV][NDM];
        __shared__ float rn[NV];
        int w = t >> 5, lane = t & 31;
        if (w < NV) {
            float s = 0.f;
            for (int d = lane; d < NDM; d += 32) {
                float x = penta[(e * NV + w) * NDM + d];
                s += x * x;
            }
            for (int off = 16; off; off >>= 1) s += __shfl_xor_sync(0xffffffffu, s, off);
            if (lane == 0) rn[w] = rsqrtf(s);
        }
        __syncthreads();
        for (int i = t; i < NV * NDM; i += 512) {
            int v = i >> 7, d = i & 127;
            dirs[v][d] = penta[(e * NV + v) * NDM + d] * rn[v];
        }
        __syncthreads();
        for (int i = t; i < NS * NV; i += 512) {
            int s = i / NV, v = i % NV;
            float aq = 0.f, ak = 0.f;
            for (int d = 0; d < NDM; d++) {
                float dd = dirs[v][d];
                aq += q_w[(e * NS + s) * NDM + d] * dd;
                ak += k_w[(e * NS + s) * NDM + d] * dd;
            }
            g_qd[e][s][v] = aq;
            g_kd[e][s][v] = ak;
        }
        if (e == 0) {
            if (t < NE) g_aw[t] = 1.f / (1.f + expf(-alpha[t]));
            if (t == 0) {
                g_invT = 1.0f / temp[0];
                float mx = -1e30f;
                for (int i = 0; i < NV; i++) mx = fmaxf(mx, fusion_w[i]);
                float ex[NV], sm = 0.f;
                for (int i = 0; i < NV; i++) { ex[i] = expf(fusion_w[i] - mx); sm += ex[i]; }
                for (int i = 0; i < NV; i++) g_wdir[i] = ex[i] / sm;
                float coords[NE];
                for (int i = 0; i < NE; i++) {
                    double x = (double)i / 15.0;
                    x = fmax(1e-6, fmin(x, 1.0 - 1e-6));
                    double val = 0.0, fac = 0.5;
                    for (int k = 0; k < 8; k++) {
                        x *= 3.0;
                        int d = (int)x;
                        x -= (double)d;
                        if (d == 2) val += fac;
                        fac *= 0.5;
                    }
                    coords[i] = (float)val;
                }
                for (int ee = 0; ee < NE; ee++) {
                    float key[NE]; int ord[NE];
                    for (int i = 0; i < NE; i++) { key[i] = fabsf(coords[i] - coords[ee]); ord[i] = i; }
                    for (int i = 1; i < NE; i++) {
                        float kv = key[i]; int ov = ord[i]; int j = i - 1;
                        while (j >= 0 && key[j] > kv) { key[j + 1] = key[j]; ord[j + 1] = ord[j]; j--; }
                        key[j + 1] = kv; ord[j + 1] = ov;
                    }
                    for (int wv = 0; wv < NW; wv++) g_routes[ee][wv] = ord[wv];
                }
            }
        }
    } else {
        // dispatch: warp = expert, ballot compaction
        __shared__ float sf[NP];
        for (int i = t; i < NP; i += 512) sf[i] = fp[i];
        __syncthreads();
        int w = t >> 5, l = t & 31;
        float lo = (float)w / 16.0f, hi = (float)(w + 1) / 16.0f;
        unsigned lmask = (1u << l) - 1u;
        int cnt = 0;
        for (int base = 0; base < NP; base += 32) {
            float f = sf[base + l];
            bool m = (f >= lo) && ((w == NE - 1) ? (f <= hi) : (f < hi));
            unsigned bal = __ballot_sync(0xffffffffu, m);
            if (m) {
                int pos = cnt + __popc(bal & lmask);
                if (pos < NC) g_idx[w][pos] = base + l;
            }
            cnt += __popc(bal);
        }
        int vcnt = min(cnt, NC);
        if (l == 0) g_cnt[w] = vcnt;
        cnt = vcnt;
        for (int base = 0; base < NP && cnt < NC; base += 32) {
            float f = sf[base + l];
            bool m = (f >= lo) && ((w == NE - 1) ? (f <= hi) : (f < hi));
            bool im = !m;
            unsigned bal = __ballot_sync(0xffffffffu, im);
            if (im) {
                int pos = cnt + __popc(bal & lmask);
                if (pos < NC) g_idx[w][pos] = base + l;
            }
            cnt += __popc(bal);
        }
    }
}

// ---------------- K zero output ----------------
__global__ __launch_bounds__(256) void k_zero(float* __restrict__ out, int n4)
{
    int i = blockIdx.x * blockDim.x + threadIdx.x;
    if (i < n4) reinterpret_cast<float4*>(out)[i] = make_float4(0.f, 0.f, 0.f, 0.f);
}

// ---------------- K2: gather + gate + affinities + V projection ----------------
struct __align__(16) Smem2 {
    float featsT[NS][132];   // [s][local row]
    float vw[NS][NDM];
    float qkd[NS][12];       // qd[0..4], kd[5..9]
    float w1[NS][16];
    float b1[16];
    float w2[16];
    float red[2][NV][8];
    int   idxs[128];
    float b2;
};

__global__ __launch_bounds__(256, 3) void k_featproc(
    const float* __restrict__ tokens, const float* __restrict__ gw1,
    const float* __restrict__ gb1, const float* __restrict__ gw2,
    const float* __restrict__ gb2, const float* __restrict__ vwg)
{
    extern __shared__ char smraw[];
    Smem2& Sm = *reinterpret_cast<Smem2*>(smraw);
    int e = blockIdx.x, b = blockIdx.y, half = blockIdx.z, t = threadIdx.x;
    int i0 = half * 128;
    int cnt = g_cnt[e];
    int nvloc = cnt - i0;
    if (nvloc < 0) nvloc = 0;
    if (nvloc > 128) nvloc = 128;

    if (nvloc == 0) {
        float4 z4 = make_float4(0.f, 0.f, 0.f, 0.f);
        float4* vb = reinterpret_cast<float4*>(&g_vbuf[e][b][i0][0]);
        for (int idx = t; idx < 128 * 32; idx += 256) vb[idx] = z4;
        for (int idx = t; idx < NV * 128; idx += 256) {
            int v = idx >> 7, ii = idx & 127;
            g_qaff[e][v][b][i0 + ii] = 0.f;
            g_kaff[e][v][b][i0 + ii] = 0.f;
        }
        if (t < NV) {
            g_kmax[e][t][b][half] = -INFINITY;
            g_kmin[e][t][b][half] = INFINITY;
        }
        return;
    }

    // ---- loads ----
    if (t < 128) Sm.idxs[t] = g_idx[e][i0 + t];
    for (int idx = t; idx < NS * 16; idx += 256) Sm.w1[idx >> 4][idx & 15] = gw1[e * NS * 16 + idx];
    if (t < 16) { Sm.b1[t] = gb1[e * 16 + t]; Sm.w2[t] = gw2[e * 16 + t]; }
    if (t == 0) Sm.b2 = gb2[e];
    for (int idx = t; idx < NS * NV; idx += 256) {
        int s = idx / NV, v = idx % NV;
        Sm.qkd[s][v]     = g_qd[e][s][v];
        Sm.qkd[s][5 + v] = g_kd[e][s][v];
    }
    {
        const float4* src = reinterpret_cast<const float4*>(vwg + e * NS * NDM);
        float4* dst = reinterpret_cast<float4*>(&Sm.vw[0][0]);
        for (int idx = t; idx < NS * NDM / 4; idx += 256) dst[idx] = src[idx];
    }
    __syncthreads();

    // ---- gather (warp per row); zero rows beyond cnt ----
    {
        int w = t >> 5, l = t & 31;
        for (int r = w; r < 128; r += 8) {
            float2 v2 = make_float2(0.f, 0.f);
            if (r < nvloc) {
                const float* src = tokens + ((size_t)b * NP + Sm.idxs[r]) * 1024 + e * NS;
                v2 = reinterpret_cast<const float2*>(src)[l];
            }
            Sm.featsT[2 * l][r]     = v2.x;
            Sm.featsT[2 * l + 1][r] = v2.y;
        }
    }
    __syncthreads();

    // ---- gate + scale + affinities : pair of threads per row (h = s-half) ----
    float aw = g_aw[e];
    {
        int r = t >> 1, h = t & 1;
        int sbase = h << 5;
        ull h2[8];
#pragma unroll
        for (int k = 0; k < 8; k++)
            h2[k] = h ? 0ull : pack2(Sm.b1[2 * k], Sm.b1[2 * k + 1]);
        for (int s = sbase; s < sbase + 32; s++) {
            float f = Sm.featsT[s][r];
            ull f2 = pack2(f, f);
            const ulonglong2* wp = reinterpret_cast<const ulonglong2*>(&Sm.w1[s][0]);
#pragma unroll
            for (int j = 0; j < 4; j++) {
                ulonglong2 wv = wp[j];
                h2[2 * j]     = fma2(f2, wv.x, h2[2 * j]);
                h2[2 * j + 1] = fma2(f2, wv.y, h2[2 * j + 1]);
            }
        }
        float hv[16];
#pragma unroll
        for (int k = 0; k < 8; k++) {
            float2 u = unpack2(h2[k]);
            hv[2 * k] = u.x; hv[2 * k + 1] = u.y;
        }
#pragma unroll
        for (int k = 0; k < 16; k++)
            hv[k] += __shfl_xor_sync(0xffffffffu, hv[k], 1);
        float op = 0.f;
#pragma unroll
        for (int k = 0; k < 8; k++) {
            int kk = (h << 3) + k;
            op += geluf(hv[kk]) * Sm.w2[kk];
        }
        op += __shfl_xor_sync(0xffffffffu, op, 1);
        float o = Sm.b2 + op;
        float gsig  = 1.f / (1.f + __expf(-o));
        float scale = gsig * aw + (1.f - aw);

        float qa[NV], ka[NV];
#pragma unroll
        for (int v = 0; v < NV; v++) { qa[v] = 0.f; ka[v] = 0.f; }
        for (int s = sbase; s < sbase + 32; s++) {
            float f = Sm.featsT[s][r] * scale;
            Sm.featsT[s][r] = f;
            float4 c0 = *reinterpret_cast<const float4*>(&Sm.qkd[s][0]);
            float4 c1 = *reinterpret_cast<const float4*>(&Sm.qkd[s][4]);
            float4 c2 = *reinterpret_cast<const float4*>(&Sm.qkd[s][8]);
            qa[0] += f * c0.x; qa[1] += f * c0.y; qa[2] += f * c0.z; qa[3] += f * c0.w;
            qa[4] += f * c1.x;
            ka[0] += f * c1.y; ka[1] += f * c1.z; ka[2] += f * c1.w;
            ka[3] += f * c2.x; ka[4] += f * c2.y;
        }
#pragma unroll
        for (int v = 0; v < NV; v++) {
            qa[v] += __shfl_xor_sync(0xffffffffu, qa[v], 1);
            ka[v] += __shfl_xor_sync(0xffffffffu, ka[v], 1);
        }
        bool vl = (r < nvloc);
        if (h == 0) {
#pragma unroll
            for (int v = 0; v < NV; v++) {
                g_qaff[e][v][b][i0 + r] = qa[v];
                g_kaff[e][v][b][i0 + r] = ka[v];
            }
        }
        int w = t >> 5, lane = t & 31;
#pragma unroll
        for (int v = 0; v < NV; v++) {
            float kmx = vl ? ka[v] : -INFINITY;
            float kmn = vl ? ka[v] :  INFINITY;
            for (int off = 16; off; off >>= 1) {
                kmx = fmaxf(kmx, __shfl_xor_sync(0xffffffffu, kmx, off));
                kmn = fminf(kmn, __shfl_xor_sync(0xffffffffu, kmn, off));
            }
            if (lane == 0) { Sm.red[0][v][w] = kmx; Sm.red[1][v][w] = kmn; }
        }
    }
    __syncthreads();
    if (t < NV) {
        float mx = -INFINITY, mn = INFINITY;
        for (int w = 0; w < 8; w++) {
            mx = fmaxf(mx, Sm.red[0][t][w]);
            mn = fminf(mn, Sm.red[1][t][w]);
        }
        g_kmax[e][t][b][half] = mx;
        g_kmin[e][t][b][half] = mn;
    }

    // ---- V GEMM: 128x128 = featsT^T(128x64) @ vw(64x128), f32x2 ----
    int lane = t & 31, wi = t >> 5;
    for (int pass = 0; pass < 2; pass++) {
        int r0 = pass * 64 + wi * 8;
        ull acc[4][4];
#pragma unroll
        for (int rp = 0; rp < 4; rp++)
#pragma unroll
            for (int c = 0; c < 4; c++) acc[rp][c] = 0ull;
#pragma unroll 4
        for (int k = 0; k < NS; k++) {
            ulonglong2 a01 = *reinterpret_cast<const ulonglong2*>(&Sm.featsT[k][r0]);
            ulonglong2 a23 = *reinterpret_cast<const ulonglong2*>(&Sm.featsT[k][r0 + 4]);
            float4 bv = *reinterpret_cast<const float4*>(&Sm.vw[k][lane * 4]);
            ull ar[4] = {a01.x, a01.y, a23.x, a23.y};
            ull bc[4] = {pack2(bv.x, bv.x), pack2(bv.y, bv.y), pack2(bv.z, bv.z), pack2(bv.w, bv.w)};
#pragma unroll
            for (int rp = 0; rp < 4; rp++)
#pragma unroll
                for (int c = 0; c < 4; c++) acc[rp][c] = fma2(ar[rp], bc[c], acc[rp][c]);
        }
#pragma unroll
        for (int rp = 0; rp < 4; rp++) {
            float2 u0 = unpack2(acc[rp][0]), u1 = unpack2(acc[rp][1]);
            float2 u2 = unpack2(acc[rp][2]), u3 = unpack2(acc[rp][3]);
            int row = r0 + rp * 2;
            float* d0 = &g_vbuf[e][b][i0 + row][lane * 4];
            float* d1 = &g_vbuf[e][b][i0 + row + 1][lane * 4];
            *reinterpret_cast<float4*>(d0) = make_float4(u0.x, u1.x, u2.x, u3.x);
            *reinterpret_cast<float4*>(d1) = make_float4(u0.y, u1.y, u2.y, u3.y);
        }
    }
}

// ---------------- K3: fused multi-direction attention ----------------
struct __align__(16) Smem3 {
    float vchunk[32][132];
    float wsub[32][68];
    float kall[NV][NW * NC];
    float q2[NV][64];
    float m2[NV][64];
    float Cc[NV][64];
    float zp[NV][4][64];
    float kmaxc[NV];
    float kminc[NV];
    float wdirs[NV];
    int   idxs[64];
    int   cnt3[NW];
};

__global__ __launch_bounds__(256, 3) void k_attn(float* __restrict__ out)
{
    int e = blockIdx.x, b = blockIdx.y, it = blockIdx.z, t = threadIdx.x;
    int cnte = g_cnt[e];
    int i0 = it * 64;
    if (i0 >= cnte) return;

    extern __shared__ char smraw[];
    Smem3& Sm = *reinterpret_cast<Smem3*>(smraw);

    int nbs[NW] = {g_routes[e][0], g_routes[e][1], g_routes[e][2]};

    if (t < NW) Sm.cnt3[t] = g_cnt[nbs[t]];
    if (t < NV) {
        Sm.wdirs[t] = g_wdir[t];
        float mx = -INFINITY, mn = INFINITY;
        for (int n = 0; n < NW; n++)
            for (int h = 0; h < 2; h++) {
                mx = fmaxf(mx, g_kmax[nbs[n]][t][b][h]);
                mn = fminf(mn, g_kmin[nbs[n]][t][b][h]);
            }
        Sm.kmaxc[t] = mx;
        Sm.kminc[t] = mn;
    }
    for (int idx = t; idx < 960; idx += 256) {
        int v = idx / 192, r = idx % 192, n = r >> 6, c4 = r & 63;
        float4 val = *reinterpret_cast<const float4*>(&g_kaff[nbs[n]][v][b][c4 * 4]);
        *reinterpret_cast<float4*>(&Sm.kall[v][n * 256 + c4 * 4]) = val;
    }
    float invTl2 = g_invT * 1.4426950408889634f;
    for (int idx = t; idx < NV * 64; idx += 256) {
        int v = idx >> 6, ii = idx & 63;
        Sm.q2[v][ii] = g_qaff[e][v][b][i0 + ii] * invTl2;
    }
    if (t < 64) Sm.idxs[t] = g_idx[e][i0 + t];
    __syncthreads();

    // ---- Pass A: per-(row, dir) normalizer in log2 domain ----
    {
        int ii = t & 63, grp = t >> 6;
#pragma unroll
        for (int v = 0; v < NV; v++) {
            float q = Sm.q2[v][ii];
            float m = fmaxf(q * Sm.kmaxc[v], q * Sm.kminc[v]);
            if (grp == 0) Sm.m2[v][ii] = m;
            float nm = -m;
            float z0 = 0.f, z1 = 0.f;
            for (int n = 0; n < NW; n++) {
                int lim = Sm.cnt3[n];
                const float* kr = &Sm.kall[v][n * 256];
                for (int j = grp * 4; j < lim; j += 16) {
                    float4 kv = *reinterpret_cast<const float4*>(&kr[j]);
                    float x0 = fmaf(q, kv.x, nm);
                    float x1 = (j + 1 < lim) ? fmaf(q, kv.y, nm) : -1e30f;
                    float x2 = (j + 2 < lim) ? fmaf(q, kv.z, nm) : -1e30f;
                    float x3 = (j + 3 < lim) ? fmaf(q, kv.w, nm) : -1e30f;
                    z0 += ex2f(x0); z1 += ex2f(x1);
                    z0 += ex2f(x2); z1 += ex2f(x3);
                }
            }
            Sm.zp[v][grp][ii] = z0 + z1;
        }
    }
    __syncthreads();
    for (int idx = t; idx < NV * 64; idx += 256) {
        int v = idx / 64, iL = idx % 64;
        float Z = Sm.zp[v][0][iL] + Sm.zp[v][1][iL] + Sm.zp[v][2][iL] + Sm.zp[v][3][iL];
        Sm.Cc[v][iL] = (Z > 0.f) ? (lg2f_(Sm.wdirs[v] / Z) - Sm.m2[v][iL]) : -1e30f;
    }
    __syncthreads();

    // ---- Pass B: combined-weight GEMM over active 32-row chunks, f32x2 ----
    int i = t & 63, jgrp = t >> 6;
    float q2r[NV], Cr[NV];
#pragma unroll
    for (int v = 0; v < NV; v++) { q2r[v] = Sm.q2[v][i]; Cr[v] = Sm.Cc[v][i]; }

    int c0 = Sm.cnt3[0], c1 = Sm.cnt3[1], c2 = Sm.cnt3[2];
    int nc0 = (c0 + 31) >> 5, nc1 = (c1 + 31) >> 5, nc2 = (c2 + 31) >> 5;
    int T = nc0 + nc1 + nc2;

    int lane = t & 31, w = t >> 5;
    ull acc[4][4];
#pragma unroll
    for (int rp = 0; rp < 4; rp++)
#pragma unroll
        for (int c = 0; c < 4; c++) acc[rp][c] = 0ull;

    int vrow = t >> 5;           // rows this thread stores: vrow + k4*8? no: idx-based below
    for (int a = 0; a < T; a++) {
        int n, jl, cn;
        if (a < nc0)            { n = 0; jl = a << 5;              cn = c0; }
        else if (a < nc0 + nc1) { n = 1; jl = (a - nc0) << 5;      cn = c1; }
        else                    { n = 2; jl = (a - nc0 - nc1) << 5; cn = c2; }

        // prefetch V chunk into registers (L2 latency hidden behind W compute)
        const float4* vsrc = reinterpret_cast<const float4*>(&g_vbuf[nbs[n]][b][jl][0]);
        float4 pf0 = vsrc[t];
        float4 pf1 = vsrc[t + 256];
        float4 pf2 = vsrc[t + 512];
        float4 pf3 = vsrc[t + 768];

        // combined weights W[j][i] = sum_v exp2(q2*k + C)
        {
#pragma unroll
            for (int jj = 0; jj < 8; jj++) {
                int jloc = jgrp * 8 + jj;
                int j = n * 256 + jl + jloc;
                float wv = 0.f;
#pragma unroll
                for (int v = 0; v < NV; v++)
                    wv += ex2f(fmaf(q2r[v], Sm.kall[v][j], Cr[v]));
                if (jl + jloc >= cn) wv = 0.f;
                Sm.wsub[jloc][i] = wv;
            }
        }
        // stage V into smem
        {
            int row = t >> 5, cc = (t & 31) * 4;
            *reinterpret_cast<float4*>(&Sm.vchunk[row][cc])      = pf0;
            *reinterpret_cast<float4*>(&Sm.vchunk[row + 8][cc])  = pf1;
            *reinterpret_cast<float4*>(&Sm.vchunk[row + 16][cc]) = pf2;
            *reinterpret_cast<float4*>(&Sm.vchunk[row + 24][cc]) = pf3;
        }
        __syncthreads();
        // GEMM: out(64x128) += wsub(32x64)[k][i] @ vchunk(32x128)
#pragma unroll 4
        for (int k = 0; k < 32; k++) {
            ulonglong2 a01 = *reinterpret_cast<const ulonglong2*>(&Sm.wsub[k][w * 8]);
            ulonglong2 a23 = *reinterpret_cast<const ulonglong2*>(&Sm.wsub[k][w * 8 + 4]);
            float4 bv = *reinterpret_cast<const float4*>(&Sm.vchunk[k][lane * 4]);
            ull ar[4] = {a01.x, a01.y, a23.x, a23.y};
            ull bc[4] = {pack2(bv.x, bv.x), pack2(bv.y, bv.y), pack2(bv.z, bv.z), pack2(bv.w, bv.w)};
#pragma unroll
            for (int rp = 0; rp < 4; rp++)
#pragma unroll
                for (int c = 0; c < 4; c++) acc[rp][c] = fma2(ar[rp], bc[c], acc[rp][c]);
        }
        __syncthreads();
    }
    (void)vrow;

    // ---- store valid rows ----
#pragma unroll
    for (int rp = 0; rp < 4; rp++) {
        int row = w * 8 + rp * 2;
        float2 u0 = unpack2(acc[rp][0]), u1 = unpack2(acc[rp][1]);
        float2 u2 = unpack2(acc[rp][2]), u3 = unpack2(acc[rp][3]);
        if (i0 + row < cnte) {
            float* dst = out + ((size_t)b * NP + Sm.idxs[row]) * NDM + lane * 4;
            *reinterpret_cast<float4*>(dst) = make_float4(u0.x, u1.x, u2.x, u3.x);
        }
        if (i0 + row + 1 < cnte) {
            float* dst = out + ((size_t)b * NP + Sm.idxs[row + 1]) * NDM + lane * 4;
            *reinterpret_cast<float4*>(dst) = make_float4(u0.y, u1.y, u2.y, u3.y);
        }
    }
}

// ---------------- launch ----------------
extern "C" void kernel_launch(void* const* d_in, const int* in_sizes, int n_in,
                              void* d_out, int out_size)
{
    const float* tokens  = (const float*)d_in[0];
    const float* fingerp = (const float*)d_in[1];
    const float* alpha   = (const float*)d_in[2];
    const float* gw1     = (const float*)d_in[3];
    const float* gb1     = (const float*)d_in[4];
    const float* gw2     = (const float*)d_in[5];
    const float* gb2     = (const float*)d_in[6];
    const float* q_w     = (const float*)d_in[7];
    const float* k_w     = (const float*)d_in[8];
    const float* v_w     = (const float*)d_in[9];
    const float* penta   = (const float*)d_in[10];
    const float* fusion  = (const float*)d_in[11];
    const float* temp    = (const float*)d_in[12];
    float* out = (float*)d_out;

    cudaFuncSetAttribute(k_featproc, cudaFuncAttributeMaxDynamicSharedMemorySize, (int)sizeof(Smem2));
    cudaFuncSetAttribute(k_attn,     cudaFuncAttributeMaxDynamicSharedMemorySize, (int)sizeof(Smem3));

    k_init<<<NE + 1, 512>>>(alpha, penta, fusion, q_w, k_w, temp, fingerp);
    int n4 = out_size / 4;
    k_zero<<<(n4 + 255) / 256, 256>>>(out, n4);
    k_featproc<<<dim3(NE, NB, 2), 256, sizeof(Smem2)>>>(tokens, gw1, gb1, gw2, gb2, v_w);
    k_attn<<<dim3(NE, NB, 4), 256, sizeof(Smem3)>>>(out);
}